// round 5
// baseline (speedup 1.0000x reference)
#include <cuda_runtime.h>
#include <cstdint>

#define N_NODES_MAX 50000
#define N_EDGES_MAX 1600000
#define IN_DIM 128
#define QKV_DIM 128   // OUT_DIM * N_HEADS = 16*8

typedef unsigned long long ull;

// ---------------- device scratch (allocation-free rule: __device__ globals) ----
__device__ float g_Q[(size_t)N_NODES_MAX * QKV_DIM];
__device__ float g_K[(size_t)N_NODES_MAX * QKV_DIM];
__device__ float g_V[(size_t)N_NODES_MAX * QKV_DIM];
__device__ int   g_off[N_NODES_MAX + 1];
__device__ int   g_cur[N_NODES_MAX];
__device__ int   g_srcs[N_EDGES_MAX];

// ---------------- f32x2 packed helpers (sm_100+) ------------------------------
__device__ __forceinline__ ull fma2(ull a, ull b, ull c) {
    ull d;
    asm("fma.rn.f32x2 %0, %1, %2, %3;" : "=l"(d) : "l"(a), "l"(b), "l"(c));
    return d;
}
__device__ __forceinline__ ull dup2(float x) {
    unsigned int u = __float_as_uint(x);
    ull r;
    asm("mov.b64 %0, {%1, %2};" : "=l"(r) : "r"(u), "r"(u));
    return r;
}
__device__ __forceinline__ void unpack2(ull v, float& lo, float& hi) {
    unsigned int a, b;
    asm("mov.b64 {%0, %1}, %2;" : "=r"(a), "=r"(b) : "l"(v));
    lo = __uint_as_float(a);
    hi = __uint_as_float(b);
}

// ---------------- kernel 0: zero counters -------------------------------------
__global__ void zero_off_kernel(int n) {
    int i = blockIdx.x * blockDim.x + threadIdx.x;
    if (i <= n) g_off[i] = 0;
}

// ---------------- kernel 1: fused QKV projection GEMM -------------------------
// O = h @ W + b  for W in {Wq,Wk,Wv} selected by blockIdx.y.
// Tile: 64 nodes x 128 cols per block, 256 threads, thread tile 8 nodes x 4 cols,
// accumulators packed as f32x2 over node pairs.
__global__ void __launch_bounds__(256, 4)
proj_kernel(const float* __restrict__ h,
            const float* __restrict__ Wq, const float* __restrict__ bq,
            const float* __restrict__ Wk, const float* __restrict__ bk,
            const float* __restrict__ Wv, const float* __restrict__ bv,
            int nN)
{
    __shared__ __align__(16) float ws[32 * 128];   // ws[k][col], k-chunk of 32
    __shared__ __align__(16) float hs[32 * 66];    // hs[k][node], stride 66 (even, padded)

    const float* W;
    const float* b;
    float* O;
    if (blockIdx.y == 0)      { W = Wq; b = bq; O = g_Q; }
    else if (blockIdx.y == 1) { W = Wk; b = bk; O = g_K; }
    else                      { W = Wv; b = bv; O = g_V; }

    const int m0 = blockIdx.x * 64;
    const int t  = threadIdx.x;
    const int tx = t & 31;   // col group: cols tx*4 .. tx*4+3
    const int ty = t >> 5;   // node group: nodes ty*8 .. ty*8+7 (4 pairs)

    ull acc[4][4];
#pragma unroll
    for (int p = 0; p < 4; p++)
#pragma unroll
        for (int c = 0; c < 4; c++) acc[p][c] = 0ull;

    for (int k0 = 0; k0 < IN_DIM; k0 += 32) {
        // load W chunk [32][128]: 1024 float4, 4 per thread, coalesced
#pragma unroll
        for (int i = 0; i < 4; i++) {
            int g  = t + i * 256;
            int r  = g >> 5;
            int cq = g & 31;
            float4 w = *(const float4*)(W + (size_t)(k0 + r) * QKV_DIM + cq * 4);
            *(float4*)&ws[r * 128 + cq * 4] = w;
        }
        // load h chunk [64 nodes][32 k] transposed into hs[k][node]
#pragma unroll
        for (int i = 0; i < 2; i++) {
            int f    = t + i * 256;
            int node = f >> 3;
            int kq   = f & 7;
            float4 hv = make_float4(0.f, 0.f, 0.f, 0.f);
            if (m0 + node < nN)
                hv = *(const float4*)(h + (size_t)(m0 + node) * IN_DIM + k0 + kq * 4);
            hs[(kq * 4 + 0) * 66 + node] = hv.x;
            hs[(kq * 4 + 1) * 66 + node] = hv.y;
            hs[(kq * 4 + 2) * 66 + node] = hv.z;
            hs[(kq * 4 + 3) * 66 + node] = hv.w;
        }
        __syncthreads();

#pragma unroll 8
        for (int k = 0; k < 32; k++) {
            float4 w4 = *(const float4*)&ws[k * 128 + tx * 4];
            ull wd0 = dup2(w4.x), wd1 = dup2(w4.y), wd2 = dup2(w4.z), wd3 = dup2(w4.w);
#pragma unroll
            for (int p = 0; p < 4; p++) {
                ull hp = *(const ull*)&hs[k * 66 + ty * 8 + 2 * p];
                acc[p][0] = fma2(wd0, hp, acc[p][0]);
                acc[p][1] = fma2(wd1, hp, acc[p][1]);
                acc[p][2] = fma2(wd2, hp, acc[p][2]);
                acc[p][3] = fma2(wd3, hp, acc[p][3]);
            }
        }
        __syncthreads();
    }

    // epilogue: add bias, store per-node float4
    float4 bb = *(const float4*)(b + tx * 4);
#pragma unroll
    for (int p = 0; p < 4; p++) {
        float lo0, hi0, lo1, hi1, lo2, hi2, lo3, hi3;
        unpack2(acc[p][0], lo0, hi0);
        unpack2(acc[p][1], lo1, hi1);
        unpack2(acc[p][2], lo2, hi2);
        unpack2(acc[p][3], lo3, hi3);
        int n0 = m0 + ty * 8 + 2 * p;
        if (n0 < nN) {
            float4 o = make_float4(lo0 + bb.x, lo1 + bb.y, lo2 + bb.z, lo3 + bb.w);
            *(float4*)(O + (size_t)n0 * QKV_DIM + tx * 4) = o;
        }
        if (n0 + 1 < nN) {
            float4 o = make_float4(hi0 + bb.x, hi1 + bb.y, hi2 + bb.z, hi3 + bb.w);
            *(float4*)(O + (size_t)(n0 + 1) * QKV_DIM + tx * 4) = o;
        }
    }
}

// ---------------- kernel 2: histogram of dst -----------------------------------
__global__ void hist_kernel(const int* __restrict__ dst, int nE) {
    int e = blockIdx.x * blockDim.x + threadIdx.x;
    if (e < nE) atomicAdd(&g_off[dst[e] + 1], 1);
}

// ---------------- kernel 3: single-block inclusive scan over g_off[1..n] -------
__global__ void scan_kernel(int n) {
    __shared__ int buf[1024];
    __shared__ int s_carry;
    int t = threadIdx.x;
    if (t == 0) s_carry = 0;
    __syncthreads();
    for (int base = 1; base <= n; base += 1024) {
        int i = base + t;
        int v = (i <= n) ? g_off[i] : 0;
        buf[t] = v;
        __syncthreads();
        for (int d = 1; d < 1024; d <<= 1) {
            int x = (t >= d) ? buf[t - d] : 0;
            __syncthreads();
            buf[t] += x;
            __syncthreads();
        }
        int c = s_carry;
        if (i <= n) g_off[i] = buf[t] + c;
        int tot = buf[1023];
        __syncthreads();
        if (t == 0) s_carry = c + tot;
        __syncthreads();
    }
}

// ---------------- kernel 4: cursor = offsets ------------------------------------
__global__ void copy_cur_kernel(int n) {
    int i = blockIdx.x * blockDim.x + threadIdx.x;
    if (i < n) g_cur[i] = g_off[i];
}

// ---------------- kernel 5: scatter src ids into dst-CSR order ------------------
__global__ void scatter_kernel(const int* __restrict__ src, const int* __restrict__ dst, int nE) {
    int e = blockIdx.x * blockDim.x + threadIdx.x;
    if (e < nE) {
        int d = dst[e];
        int p = atomicAdd(&g_cur[d], 1);
        g_srcs[p] = src[e];
    }
}

// ---------------- kernel 6: per-node pull attention (one warp per dst node) -----
__global__ void __launch_bounds__(256)
consume_kernel(float* __restrict__ out, int nN) {
    int w    = (blockIdx.x * blockDim.x + threadIdx.x) >> 5;
    int lane = threadIdx.x & 31;
    if (w >= nN) return;

    const float4* Q4 = (const float4*)g_Q;
    const float4* K4 = (const float4*)g_K;
    const float4* V4 = (const float4*)g_V;

    int beg = g_off[w];
    int end = g_off[w + 1];

    // lane handles elements lane*4..lane*4+3 of 128-vector -> head = lane/4
    float4 q   = Q4[(size_t)w * 32 + lane];
    float4 acc = make_float4(0.f, 0.f, 0.f, 0.f);
    float  z   = 0.f;

    int j = beg;
    for (; j + 1 < end; j += 2) {
        int s0 = g_srcs[j];
        int s1 = g_srcs[j + 1];
        float4 k0 = K4[(size_t)s0 * 32 + lane];
        float4 k1 = K4[(size_t)s1 * 32 + lane];
        float4 v0 = V4[(size_t)s0 * 32 + lane];
        float4 v1 = V4[(size_t)s1 * 32 + lane];

        float p0 = k0.x * q.x + k0.y * q.y + k0.z * q.z + k0.w * q.w;
        float p1 = k1.x * q.x + k1.y * q.y + k1.z * q.z + k1.w * q.w;
        p0 += __shfl_xor_sync(0xffffffffu, p0, 1);
        p0 += __shfl_xor_sync(0xffffffffu, p0, 2);
        p1 += __shfl_xor_sync(0xffffffffu, p1, 1);
        p1 += __shfl_xor_sync(0xffffffffu, p1, 2);

        float sc0 = __expf(fminf(fmaxf(p0 * 0.25f, -5.f), 5.f));
        float sc1 = __expf(fminf(fmaxf(p1 * 0.25f, -5.f), 5.f));

        acc.x = fmaf(v0.x, sc0, fmaf(v1.x, sc1, acc.x));
        acc.y = fmaf(v0.y, sc0, fmaf(v1.y, sc1, acc.y));
        acc.z = fmaf(v0.z, sc0, fmaf(v1.z, sc1, acc.z));
        acc.w = fmaf(v0.w, sc0, fmaf(v1.w, sc1, acc.w));
        z += sc0 + sc1;
    }
    if (j < end) {
        int s0 = g_srcs[j];
        float4 k0 = K4[(size_t)s0 * 32 + lane];
        float4 v0 = V4[(size_t)s0 * 32 + lane];
        float p0 = k0.x * q.x + k0.y * q.y + k0.z * q.z + k0.w * q.w;
        p0 += __shfl_xor_sync(0xffffffffu, p0, 1);
        p0 += __shfl_xor_sync(0xffffffffu, p0, 2);
        float sc0 = __expf(fminf(fmaxf(p0 * 0.25f, -5.f), 5.f));
        acc.x = fmaf(v0.x, sc0, acc.x);
        acc.y = fmaf(v0.y, sc0, acc.y);
        acc.z = fmaf(v0.z, sc0, acc.z);
        acc.w = fmaf(v0.w, sc0, acc.w);
        z += sc0;
    }

    float inv = 1.f / (z + 1e-6f);
    float4 o = make_float4(acc.x * inv, acc.y * inv, acc.z * inv, acc.w * inv);
    *(float4*)(out + (size_t)w * QKV_DIM + lane * 4) = o;
}

// ---------------- launch ---------------------------------------------------------
extern "C" void kernel_launch(void* const* d_in, const int* in_sizes, int n_in,
                              void* d_out, int out_size)
{
    const float* h  = (const float*)d_in[0];
    const float* Wq = (const float*)d_in[1];
    const float* bq = (const float*)d_in[2];
    const float* Wk = (const float*)d_in[3];
    const float* bk = (const float*)d_in[4];
    const float* Wv = (const float*)d_in[5];
    const float* bv = (const float*)d_in[6];
    const int*   src = (const int*)d_in[7];
    const int*   dst = (const int*)d_in[8];

    int nN = in_sizes[0] / IN_DIM;
    int nE = in_sizes[7];
    if (nN > N_NODES_MAX) nN = N_NODES_MAX;
    if (nE > N_EDGES_MAX) nE = N_EDGES_MAX;

    float* out = (float*)d_out;

    // 0) zero offset/count array
    zero_off_kernel<<<(nN + 1 + 255) / 256, 256>>>(nN);

    // 1) fused QKV projection
    dim3 pgrid((nN + 63) / 64, 3);
    proj_kernel<<<pgrid, 256>>>(h, Wq, bq, Wk, bk, Wv, bv, nN);

    // 2) build dst-CSR
    hist_kernel<<<(nE + 255) / 256, 256>>>(dst, nE);
    scan_kernel<<<1, 1024>>>(nN);
    copy_cur_kernel<<<(nN + 255) / 256, 256>>>(nN);
    scatter_kernel<<<(nE + 255) / 256, 256>>>(src, dst, nE);

    // 3) pull-style attention, one warp per destination node, fused normalize
    int nWarps  = nN;
    int nBlocks = (nWarps + 7) / 8;   // 8 warps (256 threads) per block
    consume_kernel<<<nBlocks, 256>>>(out, nN);

    (void)n_in; (void)out_size;
}

// round 6
// speedup vs baseline: 1.2632x; 1.2632x over previous
#include <cuda_runtime.h>
#include <cstdint>

#define N_NODES_MAX 50000
#define N_EDGES_MAX 1600000
#define IN_DIM 128
#define QKV_DIM 128   // OUT_DIM * N_HEADS = 16*8

typedef unsigned long long ull;

// ---------------- device scratch (allocation-free rule: __device__ globals) ----
__device__ float g_Q[(size_t)N_NODES_MAX * QKV_DIM];
__device__ float g_K[(size_t)N_NODES_MAX * QKV_DIM];
__device__ float g_V[(size_t)N_NODES_MAX * QKV_DIM];
__device__ int   g_off[N_NODES_MAX + 1];
__device__ int   g_cur[N_NODES_MAX];
__device__ int   g_srcs[N_EDGES_MAX];
__device__ int   g_bsum[64];

// ---------------- f32x2 packed helpers (sm_100+) ------------------------------
__device__ __forceinline__ ull fma2(ull a, ull b, ull c) {
    ull d;
    asm("fma.rn.f32x2 %0, %1, %2, %3;" : "=l"(d) : "l"(a), "l"(b), "l"(c));
    return d;
}
__device__ __forceinline__ ull dup2(float x) {
    unsigned int u = __float_as_uint(x);
    ull r;
    asm("mov.b64 %0, {%1, %2};" : "=l"(r) : "r"(u), "r"(u));
    return r;
}
__device__ __forceinline__ void unpack2(ull v, float& lo, float& hi) {
    unsigned int a, b;
    asm("mov.b64 {%0, %1}, %2;" : "=r"(a), "=r"(b) : "l"(v));
    lo = __uint_as_float(a);
    hi = __uint_as_float(b);
}

// ---------------- kernel 0: zero counters -------------------------------------
__global__ void zero_off_kernel(int n) {
    int i = blockIdx.x * blockDim.x + threadIdx.x;
    if (i <= n) g_off[i] = 0;
}

// ---------------- kernel 1: fused QKV projection GEMM -------------------------
__global__ void __launch_bounds__(256, 4)
proj_kernel(const float* __restrict__ h,
            const float* __restrict__ Wq, const float* __restrict__ bq,
            const float* __restrict__ Wk, const float* __restrict__ bk,
            const float* __restrict__ Wv, const float* __restrict__ bv,
            int nN)
{
    __shared__ __align__(16) float ws[32 * 128];   // ws[k][col]
    __shared__ __align__(16) float hs[32 * 66];    // hs[k][node], pad 66

    const float* W;
    const float* b;
    float* O;
    if (blockIdx.y == 0)      { W = Wq; b = bq; O = g_Q; }
    else if (blockIdx.y == 1) { W = Wk; b = bk; O = g_K; }
    else                      { W = Wv; b = bv; O = g_V; }

    const int m0 = blockIdx.x * 64;
    const int t  = threadIdx.x;
    const int tx = t & 31;   // cols tx*4 .. tx*4+3
    const int ty = t >> 5;   // nodes ty*8 .. ty*8+7

    ull acc[4][4];
#pragma unroll
    for (int p = 0; p < 4; p++)
#pragma unroll
        for (int c = 0; c < 4; c++) acc[p][c] = 0ull;

    for (int k0 = 0; k0 < IN_DIM; k0 += 32) {
#pragma unroll
        for (int i = 0; i < 4; i++) {
            int g  = t + i * 256;
            int r  = g >> 5;
            int cq = g & 31;
            float4 w = *(const float4*)(W + (size_t)(k0 + r) * QKV_DIM + cq * 4);
            *(float4*)&ws[r * 128 + cq * 4] = w;
        }
#pragma unroll
        for (int i = 0; i < 2; i++) {
            int f    = t + i * 256;
            int node = f >> 3;
            int kq   = f & 7;
            float4 hv = make_float4(0.f, 0.f, 0.f, 0.f);
            if (m0 + node < nN)
                hv = *(const float4*)(h + (size_t)(m0 + node) * IN_DIM + k0 + kq * 4);
            hs[(kq * 4 + 0) * 66 + node] = hv.x;
            hs[(kq * 4 + 1) * 66 + node] = hv.y;
            hs[(kq * 4 + 2) * 66 + node] = hv.z;
            hs[(kq * 4 + 3) * 66 + node] = hv.w;
        }
        __syncthreads();

#pragma unroll 8
        for (int k = 0; k < 32; k++) {
            float4 w4 = *(const float4*)&ws[k * 128 + tx * 4];
            ull wd0 = dup2(w4.x), wd1 = dup2(w4.y), wd2 = dup2(w4.z), wd3 = dup2(w4.w);
#pragma unroll
            for (int p = 0; p < 4; p++) {
                ull hp = *(const ull*)&hs[k * 66 + ty * 8 + 2 * p];
                acc[p][0] = fma2(wd0, hp, acc[p][0]);
                acc[p][1] = fma2(wd1, hp, acc[p][1]);
                acc[p][2] = fma2(wd2, hp, acc[p][2]);
                acc[p][3] = fma2(wd3, hp, acc[p][3]);
            }
        }
        __syncthreads();
    }

    float4 bb = *(const float4*)(b + tx * 4);
#pragma unroll
    for (int p = 0; p < 4; p++) {
        float lo0, hi0, lo1, hi1, lo2, hi2, lo3, hi3;
        unpack2(acc[p][0], lo0, hi0);
        unpack2(acc[p][1], lo1, hi1);
        unpack2(acc[p][2], lo2, hi2);
        unpack2(acc[p][3], lo3, hi3);
        int n0 = m0 + ty * 8 + 2 * p;
        if (n0 < nN) {
            float4 o = make_float4(lo0 + bb.x, lo1 + bb.y, lo2 + bb.z, lo3 + bb.w);
            *(float4*)(O + (size_t)n0 * QKV_DIM + tx * 4) = o;
        }
        if (n0 + 1 < nN) {
            float4 o = make_float4(hi0 + bb.x, hi1 + bb.y, hi2 + bb.z, hi3 + bb.w);
            *(float4*)(O + (size_t)(n0 + 1) * QKV_DIM + tx * 4) = o;
        }
    }
}

// ---------------- kernel 2: histogram of dst -----------------------------------
__global__ void hist_kernel(const int* __restrict__ dst, int nE) {
    int e = blockIdx.x * blockDim.x + threadIdx.x;
    if (e < nE) atomicAdd(&g_off[dst[e] + 1], 1);
}

// ---------------- scan phase A: per-block inclusive scan of g_off[1..n] ---------
__global__ void __launch_bounds__(1024)
block_scan_kernel(int n) {
    __shared__ int wsum[32];
    int t    = threadIdx.x;
    int lane = t & 31;
    int wid  = t >> 5;
    int i = blockIdx.x * 1024 + t + 1;          // index into g_off
    int x = (i <= n) ? g_off[i] : 0;
    // warp inclusive scan
#pragma unroll
    for (int d = 1; d < 32; d <<= 1) {
        int y = __shfl_up_sync(0xffffffffu, x, d);
        if (lane >= d) x += y;
    }
    if (lane == 31) wsum[wid] = x;
    __syncthreads();
    if (wid == 0) {
        int s = wsum[lane];
#pragma unroll
        for (int d = 1; d < 32; d <<= 1) {
            int y = __shfl_up_sync(0xffffffffu, s, d);
            if (lane >= d) s += y;
        }
        wsum[lane] = s;
    }
    __syncthreads();
    if (wid > 0) x += wsum[wid - 1];
    if (i <= n) g_off[i] = x;
    if (t == 1023) g_bsum[blockIdx.x] = x;       // block total
}

// ---------------- scan phase B: exclusive scan of block totals (tiny) -----------
__global__ void bsum_scan_kernel(int nb) {
    if (threadIdx.x == 0) {
        int acc = 0;
        for (int b = 0; b < nb; b++) {
            int v = g_bsum[b];
            g_bsum[b] = acc;
            acc += v;
        }
    }
}

// ---------------- scan phase C: add block bases + init cursors ------------------
__global__ void __launch_bounds__(1024)
scan_add_kernel(int n) {
    int t = threadIdx.x;
    int i = blockIdx.x * 1024 + t + 1;
    int add = g_bsum[blockIdx.x];
    if (i <= n) {
        int v = g_off[i] + add;
        g_off[i] = v;
        if (i < n) g_cur[i] = v;
    }
    if (blockIdx.x == 0 && t == 0) g_cur[0] = 0;
}

// ---------------- kernel 5: scatter src ids into dst-CSR order ------------------
__global__ void scatter_kernel(const int* __restrict__ src, const int* __restrict__ dst, int nE) {
    int e = blockIdx.x * blockDim.x + threadIdx.x;
    if (e < nE) {
        int d = dst[e];
        int p = atomicAdd(&g_cur[d], 1);
        g_srcs[p] = src[e];
    }
}

// ---------------- kernel 6: per-node pull attention (one warp per dst node) -----
__global__ void __launch_bounds__(256)
consume_kernel(float* __restrict__ out, int nN) {
    int w    = (blockIdx.x * blockDim.x + threadIdx.x) >> 5;
    int lane = threadIdx.x & 31;
    if (w >= nN) return;

    const float4* Q4 = (const float4*)g_Q;
    const float4* K4 = (const float4*)g_K;
    const float4* V4 = (const float4*)g_V;

    int beg = g_off[w];
    int end = g_off[w + 1];

    float4 q   = Q4[(size_t)w * 32 + lane];
    float4 acc = make_float4(0.f, 0.f, 0.f, 0.f);
    float  z   = 0.f;

    int j = beg;
    // 4-edge unrolled main loop: 8 independent LDG.128 in flight per warp
    for (; j + 3 < end; j += 4) {
        int s0 = g_srcs[j];
        int s1 = g_srcs[j + 1];
        int s2 = g_srcs[j + 2];
        int s3 = g_srcs[j + 3];
        float4 k0 = K4[(size_t)s0 * 32 + lane];
        float4 k1 = K4[(size_t)s1 * 32 + lane];
        float4 k2 = K4[(size_t)s2 * 32 + lane];
        float4 k3 = K4[(size_t)s3 * 32 + lane];
        float4 v0 = V4[(size_t)s0 * 32 + lane];
        float4 v1 = V4[(size_t)s1 * 32 + lane];
        float4 v2 = V4[(size_t)s2 * 32 + lane];
        float4 v3 = V4[(size_t)s3 * 32 + lane];

        float p0 = k0.x * q.x + k0.y * q.y + k0.z * q.z + k0.w * q.w;
        float p1 = k1.x * q.x + k1.y * q.y + k1.z * q.z + k1.w * q.w;
        float p2 = k2.x * q.x + k2.y * q.y + k2.z * q.z + k2.w * q.w;
        float p3 = k3.x * q.x + k3.y * q.y + k3.z * q.z + k3.w * q.w;
        p0 += __shfl_xor_sync(0xffffffffu, p0, 1);
        p0 += __shfl_xor_sync(0xffffffffu, p0, 2);
        p1 += __shfl_xor_sync(0xffffffffu, p1, 1);
        p1 += __shfl_xor_sync(0xffffffffu, p1, 2);
        p2 += __shfl_xor_sync(0xffffffffu, p2, 1);
        p2 += __shfl_xor_sync(0xffffffffu, p2, 2);
        p3 += __shfl_xor_sync(0xffffffffu, p3, 1);
        p3 += __shfl_xor_sync(0xffffffffu, p3, 2);

        float sc0 = __expf(fminf(fmaxf(p0 * 0.25f, -5.f), 5.f));
        float sc1 = __expf(fminf(fmaxf(p1 * 0.25f, -5.f), 5.f));
        float sc2 = __expf(fminf(fmaxf(p2 * 0.25f, -5.f), 5.f));
        float sc3 = __expf(fminf(fmaxf(p3 * 0.25f, -5.f), 5.f));

        acc.x = fmaf(v0.x, sc0, acc.x); acc.x = fmaf(v1.x, sc1, acc.x);
        acc.x = fmaf(v2.x, sc2, acc.x); acc.x = fmaf(v3.x, sc3, acc.x);
        acc.y = fmaf(v0.y, sc0, acc.y); acc.y = fmaf(v1.y, sc1, acc.y);
        acc.y = fmaf(v2.y, sc2, acc.y); acc.y = fmaf(v3.y, sc3, acc.y);
        acc.z = fmaf(v0.z, sc0, acc.z); acc.z = fmaf(v1.z, sc1, acc.z);
        acc.z = fmaf(v2.z, sc2, acc.z); acc.z = fmaf(v3.z, sc3, acc.z);
        acc.w = fmaf(v0.w, sc0, acc.w); acc.w = fmaf(v1.w, sc1, acc.w);
        acc.w = fmaf(v2.w, sc2, acc.w); acc.w = fmaf(v3.w, sc3, acc.w);
        z += (sc0 + sc1) + (sc2 + sc3);
    }
    for (; j < end; j++) {
        int s0 = g_srcs[j];
        float4 k0 = K4[(size_t)s0 * 32 + lane];
        float4 v0 = V4[(size_t)s0 * 32 + lane];
        float p0 = k0.x * q.x + k0.y * q.y + k0.z * q.z + k0.w * q.w;
        p0 += __shfl_xor_sync(0xffffffffu, p0, 1);
        p0 += __shfl_xor_sync(0xffffffffu, p0, 2);
        float sc0 = __expf(fminf(fmaxf(p0 * 0.25f, -5.f), 5.f));
        acc.x = fmaf(v0.x, sc0, acc.x);
        acc.y = fmaf(v0.y, sc0, acc.y);
        acc.z = fmaf(v0.z, sc0, acc.z);
        acc.w = fmaf(v0.w, sc0, acc.w);
        z += sc0;
    }

    float inv = 1.f / (z + 1e-6f);
    float4 o = make_float4(acc.x * inv, acc.y * inv, acc.z * inv, acc.w * inv);
    *(float4*)(out + (size_t)w * QKV_DIM + lane * 4) = o;
}

// ---------------- launch ---------------------------------------------------------
extern "C" void kernel_launch(void* const* d_in, const int* in_sizes, int n_in,
                              void* d_out, int out_size)
{
    const float* h  = (const float*)d_in[0];
    const float* Wq = (const float*)d_in[1];
    const float* bq = (const float*)d_in[2];
    const float* Wk = (const float*)d_in[3];
    const float* bk = (const float*)d_in[4];
    const float* Wv = (const float*)d_in[5];
    const float* bv = (const float*)d_in[6];
    const int*   src = (const int*)d_in[7];
    const int*   dst = (const int*)d_in[8];

    int nN = in_sizes[0] / IN_DIM;
    int nE = in_sizes[7];
    if (nN > N_NODES_MAX) nN = N_NODES_MAX;
    if (nE > N_EDGES_MAX) nE = N_EDGES_MAX;

    float* out = (float*)d_out;

    // 0) zero offset/count array
    zero_off_kernel<<<(nN + 1 + 255) / 256, 256>>>(nN);

    // 1) fused QKV projection
    dim3 pgrid((nN + 63) / 64, 3);
    proj_kernel<<<pgrid, 256>>>(h, Wq, bq, Wk, bk, Wv, bv, nN);

    // 2) build dst-CSR: histogram -> 3-phase parallel scan (+cursor init) -> scatter
    hist_kernel<<<(nE + 255) / 256, 256>>>(dst, nE);
    int nb = (nN + 1023) / 1024;
    block_scan_kernel<<<nb, 1024>>>(nN);
    bsum_scan_kernel<<<1, 32>>>(nb);
    scan_add_kernel<<<nb, 1024>>>(nN);
    scatter_kernel<<<(nE + 255) / 256, 256>>>(src, dst, nE);

    // 3) pull-style attention, one warp per destination node, fused normalize
    int nBlocks = (nN + 7) / 8;   // 8 warps (256 threads) per block
    consume_kernel<<<nBlocks, 256>>>(out, nN);

    (void)n_in; (void)out_size;
}

// round 7
// speedup vs baseline: 1.2901x; 1.0212x over previous
#include <cuda_runtime.h>
#include <cstdint>

#define N_NODES_MAX 50000
#define N_EDGES_MAX 1600000
#define IN_DIM 128
#define QKV_DIM 128   // OUT_DIM * N_HEADS = 16*8

typedef unsigned long long ull;

// ---------------- device scratch (allocation-free rule: __device__ globals) ----
__device__ float g_Q[(size_t)N_NODES_MAX * QKV_DIM];
__device__ float g_K[(size_t)N_NODES_MAX * QKV_DIM];
__device__ float g_V[(size_t)N_NODES_MAX * QKV_DIM];
__device__ int   g_off[N_NODES_MAX + 1];
__device__ int   g_cur[N_NODES_MAX];
__device__ int   g_srcs[N_EDGES_MAX];
__device__ int   g_bsum[64];

// ---------------- f32x2 packed helpers (sm_100+) ------------------------------
__device__ __forceinline__ ull fma2(ull a, ull b, ull c) {
    ull d;
    asm("fma.rn.f32x2 %0, %1, %2, %3;" : "=l"(d) : "l"(a), "l"(b), "l"(c));
    return d;
}
__device__ __forceinline__ ull dup2(float x) {
    unsigned int u = __float_as_uint(x);
    ull r;
    asm("mov.b64 %0, {%1, %2};" : "=l"(r) : "r"(u), "r"(u));
    return r;
}
__device__ __forceinline__ void unpack2(ull v, float& lo, float& hi) {
    unsigned int a, b;
    asm("mov.b64 {%0, %1}, %2;" : "=r"(a), "=r"(b) : "l"(v));
    lo = __uint_as_float(a);
    hi = __uint_as_float(b);
}

// ---------------- kernel 0: zero counters -------------------------------------
__global__ void zero_off_kernel(int n) {
    int i = blockIdx.x * blockDim.x + threadIdx.x;
    if (i <= n) g_off[i] = 0;
}

// ---------------- kernel 1: fused QKV projection GEMM -------------------------
// Block tile: 128 nodes x 128 cols, 256 threads, thread tile 8 nodes x 8 cols.
// Per k: 64B LDS per 32 fma2 -> LDS demand matches FMA issue (balanced).
#define HS_STRIDE 130
__global__ void __launch_bounds__(256, 2)
proj_kernel(const float* __restrict__ h,
            const float* __restrict__ Wq, const float* __restrict__ bq,
            const float* __restrict__ Wk, const float* __restrict__ bk,
            const float* __restrict__ Wv, const float* __restrict__ bv,
            int nN)
{
    __shared__ __align__(16) float ws[32 * 128];        // ws[k][col]
    __shared__ __align__(16) float hs[32 * HS_STRIDE];  // hs[k][node], pad

    const float* W;
    const float* b;
    float* O;
    if (blockIdx.y == 0)      { W = Wq; b = bq; O = g_Q; }
    else if (blockIdx.y == 1) { W = Wk; b = bk; O = g_K; }
    else                      { W = Wv; b = bv; O = g_V; }

    const int m0 = blockIdx.x * 128;
    const int t  = threadIdx.x;
    const int tx = t & 15;   // cols tx*8 .. tx*8+7
    const int ty = t >> 4;   // nodes ty*8 .. ty*8+7 (4 f32x2 pairs)

    ull acc[4][8];
#pragma unroll
    for (int p = 0; p < 4; p++)
#pragma unroll
        for (int c = 0; c < 8; c++) acc[p][c] = 0ull;

    for (int k0 = 0; k0 < IN_DIM; k0 += 32) {
        // W chunk [32 k][128 cols] = 1024 float4, 4 per thread
#pragma unroll
        for (int i = 0; i < 4; i++) {
            int g  = t + i * 256;
            int r  = g >> 5;
            int cq = g & 31;
            float4 w = *(const float4*)(W + (size_t)(k0 + r) * QKV_DIM + cq * 4);
            *(float4*)&ws[r * 128 + cq * 4] = w;
        }
        // h chunk [128 nodes][32 k] transposed -> hs[k][node], 1024 float4
#pragma unroll
        for (int i = 0; i < 4; i++) {
            int f    = t + i * 256;
            int node = f >> 3;     // 0..127
            int kq   = f & 7;      // k quad
            float4 hv = make_float4(0.f, 0.f, 0.f, 0.f);
            if (m0 + node < nN)
                hv = *(const float4*)(h + (size_t)(m0 + node) * IN_DIM + k0 + kq * 4);
            hs[(kq * 4 + 0) * HS_STRIDE + node] = hv.x;
            hs[(kq * 4 + 1) * HS_STRIDE + node] = hv.y;
            hs[(kq * 4 + 2) * HS_STRIDE + node] = hv.z;
            hs[(kq * 4 + 3) * HS_STRIDE + node] = hv.w;
        }
        __syncthreads();

#pragma unroll 8
        for (int k = 0; k < 32; k++) {
            float4 w0 = *(const float4*)&ws[k * 128 + tx * 8];
            float4 w1 = *(const float4*)&ws[k * 128 + tx * 8 + 4];
            ull wd[8];
            wd[0] = dup2(w0.x); wd[1] = dup2(w0.y); wd[2] = dup2(w0.z); wd[3] = dup2(w0.w);
            wd[4] = dup2(w1.x); wd[5] = dup2(w1.y); wd[6] = dup2(w1.z); wd[7] = dup2(w1.w);
#pragma unroll
            for (int p = 0; p < 4; p++) {
                ull hp = *(const ull*)&hs[k * HS_STRIDE + ty * 8 + 2 * p];
#pragma unroll
                for (int c = 0; c < 8; c++)
                    acc[p][c] = fma2(wd[c], hp, acc[p][c]);
            }
        }
        __syncthreads();
    }

    float4 b0 = *(const float4*)(b + tx * 8);
    float4 b1 = *(const float4*)(b + tx * 8 + 4);
#pragma unroll
    for (int p = 0; p < 4; p++) {
        float lo[8], hi[8];
#pragma unroll
        for (int c = 0; c < 8; c++) unpack2(acc[p][c], lo[c], hi[c]);
        int n0 = m0 + ty * 8 + 2 * p;
        if (n0 < nN) {
            float4 oa = make_float4(lo[0] + b0.x, lo[1] + b0.y, lo[2] + b0.z, lo[3] + b0.w);
            float4 ob = make_float4(lo[4] + b1.x, lo[5] + b1.y, lo[6] + b1.z, lo[7] + b1.w);
            *(float4*)(O + (size_t)n0 * QKV_DIM + tx * 8)     = oa;
            *(float4*)(O + (size_t)n0 * QKV_DIM + tx * 8 + 4) = ob;
        }
        if (n0 + 1 < nN) {
            float4 oa = make_float4(hi[0] + b0.x, hi[1] + b0.y, hi[2] + b0.z, hi[3] + b0.w);
            float4 ob = make_float4(hi[4] + b1.x, hi[5] + b1.y, hi[6] + b1.z, hi[7] + b1.w);
            *(float4*)(O + (size_t)(n0 + 1) * QKV_DIM + tx * 8)     = oa;
            *(float4*)(O + (size_t)(n0 + 1) * QKV_DIM + tx * 8 + 4) = ob;
        }
    }
}

// ---------------- kernel 2: histogram of dst -----------------------------------
__global__ void hist_kernel(const int* __restrict__ dst, int nE) {
    int e = blockIdx.x * blockDim.x + threadIdx.x;
    if (e < nE) atomicAdd(&g_off[dst[e] + 1], 1);
}

// ---------------- scan phase A: per-block inclusive scan of g_off[1..n] ---------
__global__ void __launch_bounds__(1024)
block_scan_kernel(int n) {
    __shared__ int wsum[32];
    int t    = threadIdx.x;
    int lane = t & 31;
    int wid  = t >> 5;
    int i = blockIdx.x * 1024 + t + 1;
    int x = (i <= n) ? g_off[i] : 0;
#pragma unroll
    for (int d = 1; d < 32; d <<= 1) {
        int y = __shfl_up_sync(0xffffffffu, x, d);
        if (lane >= d) x += y;
    }
    if (lane == 31) wsum[wid] = x;
    __syncthreads();
    if (wid == 0) {
        int s = wsum[lane];
#pragma unroll
        for (int d = 1; d < 32; d <<= 1) {
            int y = __shfl_up_sync(0xffffffffu, s, d);
            if (lane >= d) s += y;
        }
        wsum[lane] = s;
    }
    __syncthreads();
    if (wid > 0) x += wsum[wid - 1];
    if (i <= n) g_off[i] = x;
    if (t == 1023) g_bsum[blockIdx.x] = x;
}

// ---------------- scan phase B: exclusive scan of <=64 block totals (1 warp) ----
__global__ void bsum_scan_kernel(int nb) {
    int lane = threadIdx.x;
    int v0 = (lane < nb) ? g_bsum[lane] : 0;
    int v1 = (32 + lane < nb) ? g_bsum[32 + lane] : 0;
    int x = v0;
#pragma unroll
    for (int d = 1; d < 32; d <<= 1) {
        int y = __shfl_up_sync(0xffffffffu, x, d);
        if (lane >= d) x += y;
    }
    int tot0 = __shfl_sync(0xffffffffu, x, 31);
    int y1 = v1;
#pragma unroll
    for (int d = 1; d < 32; d <<= 1) {
        int y = __shfl_up_sync(0xffffffffu, y1, d);
        if (lane >= d) y1 += y;
    }
    // convert inclusive -> exclusive
    if (lane < nb) g_bsum[lane] = x - v0;
    if (32 + lane < nb) g_bsum[32 + lane] = tot0 + y1 - v1;
}

// ---------------- scan phase C: add block bases + init cursors ------------------
__global__ void __launch_bounds__(1024)
scan_add_kernel(int n) {
    int t = threadIdx.x;
    int i = blockIdx.x * 1024 + t + 1;
    int add = g_bsum[blockIdx.x];
    if (i <= n) {
        int v = g_off[i] + add;
        g_off[i] = v;
        if (i < n) g_cur[i] = v;
    }
    if (blockIdx.x == 0 && t == 0) g_cur[0] = 0;
}

// ---------------- kernel 5: scatter src ids into dst-CSR order ------------------
__global__ void scatter_kernel(const int* __restrict__ src, const int* __restrict__ dst, int nE) {
    int e = blockIdx.x * blockDim.x + threadIdx.x;
    if (e < nE) {
        int d = dst[e];
        int p = atomicAdd(&g_cur[d], 1);
        g_srcs[p] = src[e];
    }
}

// ---------------- kernel 6: per-node pull attention (one warp per dst node) -----
__global__ void __launch_bounds__(256)
consume_kernel(float* __restrict__ out, int nN) {
    int w    = (blockIdx.x * blockDim.x + threadIdx.x) >> 5;
    int lane = threadIdx.x & 31;
    if (w >= nN) return;

    const float4* Q4 = (const float4*)g_Q;
    const float4* K4 = (const float4*)g_K;
    const float4* V4 = (const float4*)g_V;

    int beg = g_off[w];
    int end = g_off[w + 1];

    float4 q   = Q4[(size_t)w * 32 + lane];
    float4 acc = make_float4(0.f, 0.f, 0.f, 0.f);
    float  z   = 0.f;

    int j = beg;
    for (; j + 3 < end; j += 4) {
        int s0 = g_srcs[j];
        int s1 = g_srcs[j + 1];
        int s2 = g_srcs[j + 2];
        int s3 = g_srcs[j + 3];
        float4 k0 = K4[(size_t)s0 * 32 + lane];
        float4 k1 = K4[(size_t)s1 * 32 + lane];
        float4 k2 = K4[(size_t)s2 * 32 + lane];
        float4 k3 = K4[(size_t)s3 * 32 + lane];
        float4 v0 = V4[(size_t)s0 * 32 + lane];
        float4 v1 = V4[(size_t)s1 * 32 + lane];
        float4 v2 = V4[(size_t)s2 * 32 + lane];
        float4 v3 = V4[(size_t)s3 * 32 + lane];

        float p0 = k0.x * q.x + k0.y * q.y + k0.z * q.z + k0.w * q.w;
        float p1 = k1.x * q.x + k1.y * q.y + k1.z * q.z + k1.w * q.w;
        float p2 = k2.x * q.x + k2.y * q.y + k2.z * q.z + k2.w * q.w;
        float p3 = k3.x * q.x + k3.y * q.y + k3.z * q.z + k3.w * q.w;
        p0 += __shfl_xor_sync(0xffffffffu, p0, 1);
        p0 += __shfl_xor_sync(0xffffffffu, p0, 2);
        p1 += __shfl_xor_sync(0xffffffffu, p1, 1);
        p1 += __shfl_xor_sync(0xffffffffu, p1, 2);
        p2 += __shfl_xor_sync(0xffffffffu, p2, 1);
        p2 += __shfl_xor_sync(0xffffffffu, p2, 2);
        p3 += __shfl_xor_sync(0xffffffffu, p3, 1);
        p3 += __shfl_xor_sync(0xffffffffu, p3, 2);

        float sc0 = __expf(fminf(fmaxf(p0 * 0.25f, -5.f), 5.f));
        float sc1 = __expf(fminf(fmaxf(p1 * 0.25f, -5.f), 5.f));
        float sc2 = __expf(fminf(fmaxf(p2 * 0.25f, -5.f), 5.f));
        float sc3 = __expf(fminf(fmaxf(p3 * 0.25f, -5.f), 5.f));

        acc.x = fmaf(v0.x, sc0, acc.x); acc.x = fmaf(v1.x, sc1, acc.x);
        acc.x = fmaf(v2.x, sc2, acc.x); acc.x = fmaf(v3.x, sc3, acc.x);
        acc.y = fmaf(v0.y, sc0, acc.y); acc.y = fmaf(v1.y, sc1, acc.y);
        acc.y = fmaf(v2.y, sc2, acc.y); acc.y = fmaf(v3.y, sc3, acc.y);
        acc.z = fmaf(v0.z, sc0, acc.z); acc.z = fmaf(v1.z, sc1, acc.z);
        acc.z = fmaf(v2.z, sc2, acc.z); acc.z = fmaf(v3.z, sc3, acc.z);
        acc.w = fmaf(v0.w, sc0, acc.w); acc.w = fmaf(v1.w, sc1, acc.w);
        acc.w = fmaf(v2.w, sc2, acc.w); acc.w = fmaf(v3.w, sc3, acc.w);
        z += (sc0 + sc1) + (sc2 + sc3);
    }
    for (; j < end; j++) {
        int s0 = g_srcs[j];
        float4 k0 = K4[(size_t)s0 * 32 + lane];
        float4 v0 = V4[(size_t)s0 * 32 + lane];
        float p0 = k0.x * q.x + k0.y * q.y + k0.z * q.z + k0.w * q.w;
        p0 += __shfl_xor_sync(0xffffffffu, p0, 1);
        p0 += __shfl_xor_sync(0xffffffffu, p0, 2);
        float sc0 = __expf(fminf(fmaxf(p0 * 0.25f, -5.f), 5.f));
        acc.x = fmaf(v0.x, sc0, acc.x);
        acc.y = fmaf(v0.y, sc0, acc.y);
        acc.z = fmaf(v0.z, sc0, acc.z);
        acc.w = fmaf(v0.w, sc0, acc.w);
        z += sc0;
    }

    float inv = 1.f / (z + 1e-6f);
    float4 o = make_float4(acc.x * inv, acc.y * inv, acc.z * inv, acc.w * inv);
    *(float4*)(out + (size_t)w * QKV_DIM + lane * 4) = o;
}

// ---------------- launch ---------------------------------------------------------
extern "C" void kernel_launch(void* const* d_in, const int* in_sizes, int n_in,
                              void* d_out, int out_size)
{
    const float* h  = (const float*)d_in[0];
    const float* Wq = (const float*)d_in[1];
    const float* bq = (const float*)d_in[2];
    const float* Wk = (const float*)d_in[3];
    const float* bk = (const float*)d_in[4];
    const float* Wv = (const float*)d_in[5];
    const float* bv = (const float*)d_in[6];
    const int*   src = (const int*)d_in[7];
    const int*   dst = (const int*)d_in[8];

    int nN = in_sizes[0] / IN_DIM;
    int nE = in_sizes[7];
    if (nN > N_NODES_MAX) nN = N_NODES_MAX;
    if (nE > N_EDGES_MAX) nE = N_EDGES_MAX;

    float* out = (float*)d_out;
    int nb = (nN + 1023) / 1024;

    // side stream + fork/join events for CSR chain (created once; host-side only,
    // no device memory). Work launched is identical on every call.
    static cudaStream_t s2 = nullptr;
    static cudaEvent_t  evF = nullptr, evJ = nullptr;
    if (!s2) {
        if (cudaStreamCreateWithFlags(&s2, cudaStreamNonBlocking) != cudaSuccess) s2 = nullptr;
        if (s2) {
            if (cudaEventCreateWithFlags(&evF, cudaEventDisableTiming) != cudaSuccess) evF = nullptr;
            if (cudaEventCreateWithFlags(&evJ, cudaEventDisableTiming) != cudaSuccess) evJ = nullptr;
        }
    }
    bool fork = (s2 && evF && evJ);

    dim3 pgrid((nN + 127) / 128, 3);

    if (fork) {
        // fork: CSR chain on s2, projection on the main stream, join before consume
        cudaEventRecord(evF, 0);
        cudaStreamWaitEvent(s2, evF, 0);

        zero_off_kernel<<<(nN + 1 + 255) / 256, 256, 0, s2>>>(nN);
        hist_kernel<<<(nE + 255) / 256, 256, 0, s2>>>(dst, nE);
        block_scan_kernel<<<nb, 1024, 0, s2>>>(nN);
        bsum_scan_kernel<<<1, 32, 0, s2>>>(nb);
        scan_add_kernel<<<nb, 1024, 0, s2>>>(nN);
        scatter_kernel<<<(nE + 255) / 256, 256, 0, s2>>>(src, dst, nE);
        cudaEventRecord(evJ, s2);

        proj_kernel<<<pgrid, 256>>>(h, Wq, bq, Wk, bk, Wv, bv, nN);

        cudaStreamWaitEvent(0, evJ, 0);
    } else {
        // fallback: fully serial on the main stream
        zero_off_kernel<<<(nN + 1 + 255) / 256, 256>>>(nN);
        proj_kernel<<<pgrid, 256>>>(h, Wq, bq, Wk, bk, Wv, bv, nN);
        hist_kernel<<<(nE + 255) / 256, 256>>>(dst, nE);
        block_scan_kernel<<<nb, 1024>>>(nN);
        bsum_scan_kernel<<<1, 32>>>(nb);
        scan_add_kernel<<<nb, 1024>>>(nN);
        scatter_kernel<<<(nE + 255) / 256, 256>>>(src, dst, nE);
    }

    // pull-style attention, one warp per destination node, fused normalize
    int nBlocks = (nN + 7) / 8;
    consume_kernel<<<nBlocks, 256>>>(out, nN);

    (void)n_in; (void)out_size;
}

// round 8
// speedup vs baseline: 1.4236x; 1.1035x over previous
#include <cuda_runtime.h>
#include <cuda_fp16.h>
#include <cstdint>

#define N_NODES_MAX 50000
#define N_EDGES_MAX 1600000
#define IN_DIM 128
#define QKV_DIM 128   // OUT_DIM * N_HEADS = 16*8

typedef unsigned long long ull;

// ---------------- device scratch (allocation-free rule: __device__ globals) ----
__device__ float  g_Q [(size_t)N_NODES_MAX * QKV_DIM];
__device__ __half g_Kh[(size_t)N_NODES_MAX * QKV_DIM];
__device__ __half g_Vh[(size_t)N_NODES_MAX * QKV_DIM];
__device__ int    g_off[N_NODES_MAX + 1];
__device__ int    g_cur[N_NODES_MAX];
__device__ int    g_srcs[N_EDGES_MAX];
__device__ int    g_bsum[64];

// ---------------- f32x2 packed helpers (sm_100+) ------------------------------
__device__ __forceinline__ ull fma2(ull a, ull b, ull c) {
    ull d;
    asm("fma.rn.f32x2 %0, %1, %2, %3;" : "=l"(d) : "l"(a), "l"(b), "l"(c));
    return d;
}
__device__ __forceinline__ ull dup2(float x) {
    unsigned int u = __float_as_uint(x);
    ull r;
    asm("mov.b64 %0, {%1, %2};" : "=l"(r) : "r"(u), "r"(u));
    return r;
}
__device__ __forceinline__ void unpack2(ull v, float& lo, float& hi) {
    unsigned int a, b;
    asm("mov.b64 {%0, %1}, %2;" : "=r"(a), "=r"(b) : "l"(v));
    lo = __uint_as_float(a);
    hi = __uint_as_float(b);
}
__device__ __forceinline__ unsigned int h2u(__half2 h) {
    return *reinterpret_cast<unsigned int*>(&h);
}

// ---------------- kernel 0: zero counters -------------------------------------
__global__ void zero_off_kernel(int n) {
    int i = blockIdx.x * blockDim.x + threadIdx.x;
    if (i <= n) g_off[i] = 0;
}

// ---------------- kernel 1: fused QKV projection GEMM -------------------------
// Block tile: 128 nodes x 128 cols, 256 threads, thread tile 8 nodes x 8 cols.
// Q written fp32; K/V converted + written fp16 (uint4 per node-row per thread).
#define HS_STRIDE 130
__global__ void __launch_bounds__(256, 2)
proj_kernel(const float* __restrict__ h,
            const float* __restrict__ Wq, const float* __restrict__ bq,
            const float* __restrict__ Wk, const float* __restrict__ bk,
            const float* __restrict__ Wv, const float* __restrict__ bv,
            int nN)
{
    __shared__ __align__(16) float ws[32 * 128];        // ws[k][col]
    __shared__ __align__(16) float hs[32 * HS_STRIDE];  // hs[k][node], pad

    const float* W;
    const float* b;
    if (blockIdx.y == 0)      { W = Wq; b = bq; }
    else if (blockIdx.y == 1) { W = Wk; b = bk; }
    else                      { W = Wv; b = bv; }

    const int m0 = blockIdx.x * 128;
    const int t  = threadIdx.x;
    const int tx = t & 15;   // cols tx*8 .. tx*8+7
    const int ty = t >> 4;   // nodes ty*8 .. ty*8+7 (4 f32x2 pairs)

    ull acc[4][8];
#pragma unroll
    for (int p = 0; p < 4; p++)
#pragma unroll
        for (int c = 0; c < 8; c++) acc[p][c] = 0ull;

    for (int k0 = 0; k0 < IN_DIM; k0 += 32) {
#pragma unroll
        for (int i = 0; i < 4; i++) {
            int g  = t + i * 256;
            int r  = g >> 5;
            int cq = g & 31;
            float4 w = *(const float4*)(W + (size_t)(k0 + r) * QKV_DIM + cq * 4);
            *(float4*)&ws[r * 128 + cq * 4] = w;
        }
#pragma unroll
        for (int i = 0; i < 4; i++) {
            int f    = t + i * 256;
            int node = f >> 3;
            int kq   = f & 7;
            float4 hv = make_float4(0.f, 0.f, 0.f, 0.f);
            if (m0 + node < nN)
                hv = *(const float4*)(h + (size_t)(m0 + node) * IN_DIM + k0 + kq * 4);
            hs[(kq * 4 + 0) * HS_STRIDE + node] = hv.x;
            hs[(kq * 4 + 1) * HS_STRIDE + node] = hv.y;
            hs[(kq * 4 + 2) * HS_STRIDE + node] = hv.z;
            hs[(kq * 4 + 3) * HS_STRIDE + node] = hv.w;
        }
        __syncthreads();

#pragma unroll 8
        for (int k = 0; k < 32; k++) {
            float4 w0 = *(const float4*)&ws[k * 128 + tx * 8];
            float4 w1 = *(const float4*)&ws[k * 128 + tx * 8 + 4];
            ull wd[8];
            wd[0] = dup2(w0.x); wd[1] = dup2(w0.y); wd[2] = dup2(w0.z); wd[3] = dup2(w0.w);
            wd[4] = dup2(w1.x); wd[5] = dup2(w1.y); wd[6] = dup2(w1.z); wd[7] = dup2(w1.w);
#pragma unroll
            for (int p = 0; p < 4; p++) {
                ull hp = *(const ull*)&hs[k * HS_STRIDE + ty * 8 + 2 * p];
#pragma unroll
                for (int c = 0; c < 8; c++)
                    acc[p][c] = fma2(wd[c], hp, acc[p][c]);
            }
        }
        __syncthreads();
    }

    float4 b0 = *(const float4*)(b + tx * 8);
    float4 b1 = *(const float4*)(b + tx * 8 + 4);

    if (blockIdx.y == 0) {
        // Q: fp32
#pragma unroll
        for (int p = 0; p < 4; p++) {
            float lo[8], hi[8];
#pragma unroll
            for (int c = 0; c < 8; c++) unpack2(acc[p][c], lo[c], hi[c]);
            int n0 = m0 + ty * 8 + 2 * p;
            if (n0 < nN) {
                float4 oa = make_float4(lo[0] + b0.x, lo[1] + b0.y, lo[2] + b0.z, lo[3] + b0.w);
                float4 ob = make_float4(lo[4] + b1.x, lo[5] + b1.y, lo[6] + b1.z, lo[7] + b1.w);
                *(float4*)(g_Q + (size_t)n0 * QKV_DIM + tx * 8)     = oa;
                *(float4*)(g_Q + (size_t)n0 * QKV_DIM + tx * 8 + 4) = ob;
            }
            if (n0 + 1 < nN) {
                float4 oa = make_float4(hi[0] + b0.x, hi[1] + b0.y, hi[2] + b0.z, hi[3] + b0.w);
                float4 ob = make_float4(hi[4] + b1.x, hi[5] + b1.y, hi[6] + b1.z, hi[7] + b1.w);
                *(float4*)(g_Q + (size_t)(n0 + 1) * QKV_DIM + tx * 8)     = oa;
                *(float4*)(g_Q + (size_t)(n0 + 1) * QKV_DIM + tx * 8 + 4) = ob;
            }
        }
    } else {
        // K or V: fp16, one 16B store per node-row
        __half* Oh = (blockIdx.y == 1) ? g_Kh : g_Vh;
#pragma unroll
        for (int p = 0; p < 4; p++) {
            float lo[8], hi[8];
#pragma unroll
            for (int c = 0; c < 8; c++) unpack2(acc[p][c], lo[c], hi[c]);
            int n0 = m0 + ty * 8 + 2 * p;
            if (n0 < nN) {
                uint4 u;
                u.x = h2u(__floats2half2_rn(lo[0] + b0.x, lo[1] + b0.y));
                u.y = h2u(__floats2half2_rn(lo[2] + b0.z, lo[3] + b0.w));
                u.z = h2u(__floats2half2_rn(lo[4] + b1.x, lo[5] + b1.y));
                u.w = h2u(__floats2half2_rn(lo[6] + b1.z, lo[7] + b1.w));
                *(uint4*)(Oh + (size_t)n0 * QKV_DIM + tx * 8) = u;
            }
            if (n0 + 1 < nN) {
                uint4 u;
                u.x = h2u(__floats2half2_rn(hi[0] + b0.x, hi[1] + b0.y));
                u.y = h2u(__floats2half2_rn(hi[2] + b0.z, hi[3] + b0.w));
                u.z = h2u(__floats2half2_rn(hi[4] + b1.x, hi[5] + b1.y));
                u.w = h2u(__floats2half2_rn(hi[6] + b1.z, hi[7] + b1.w));
                *(uint4*)(Oh + (size_t)(n0 + 1) * QKV_DIM + tx * 8) = u;
            }
        }
    }
}

// ---------------- kernel 2: histogram of dst -----------------------------------
__global__ void hist_kernel(const int* __restrict__ dst, int nE) {
    int e = blockIdx.x * blockDim.x + threadIdx.x;
    if (e < nE) atomicAdd(&g_off[dst[e] + 1], 1);
}

// ---------------- scan phase A: per-block inclusive scan of g_off[1..n] ---------
__global__ void __launch_bounds__(1024)
block_scan_kernel(int n) {
    __shared__ int wsum[32];
    int t    = threadIdx.x;
    int lane = t & 31;
    int wid  = t >> 5;
    int i = blockIdx.x * 1024 + t + 1;
    int x = (i <= n) ? g_off[i] : 0;
#pragma unroll
    for (int d = 1; d < 32; d <<= 1) {
        int y = __shfl_up_sync(0xffffffffu, x, d);
        if (lane >= d) x += y;
    }
    if (lane == 31) wsum[wid] = x;
    __syncthreads();
    if (wid == 0) {
        int s = wsum[lane];
#pragma unroll
        for (int d = 1; d < 32; d <<= 1) {
            int y = __shfl_up_sync(0xffffffffu, s, d);
            if (lane >= d) s += y;
        }
        wsum[lane] = s;
    }
    __syncthreads();
    if (wid > 0) x += wsum[wid - 1];
    if (i <= n) g_off[i] = x;
    if (t == 1023) g_bsum[blockIdx.x] = x;
}

// ---------------- scan phase B: exclusive scan of <=64 block totals (1 warp) ----
__global__ void bsum_scan_kernel(int nb) {
    int lane = threadIdx.x;
    int v0 = (lane < nb) ? g_bsum[lane] : 0;
    int v1 = (32 + lane < nb) ? g_bsum[32 + lane] : 0;
    int x = v0;
#pragma unroll
    for (int d = 1; d < 32; d <<= 1) {
        int y = __shfl_up_sync(0xffffffffu, x, d);
        if (lane >= d) x += y;
    }
    int tot0 = __shfl_sync(0xffffffffu, x, 31);
    int y1 = v1;
#pragma unroll
    for (int d = 1; d < 32; d <<= 1) {
        int y = __shfl_up_sync(0xffffffffu, y1, d);
        if (lane >= d) y1 += y;
    }
    if (lane < nb) g_bsum[lane] = x - v0;
    if (32 + lane < nb) g_bsum[32 + lane] = tot0 + y1 - v1;
}

// ---------------- scan phase C: add block bases + init cursors ------------------
__global__ void __launch_bounds__(1024)
scan_add_kernel(int n) {
    int t = threadIdx.x;
    int i = blockIdx.x * 1024 + t + 1;
    int add = g_bsum[blockIdx.x];
    if (i <= n) {
        int v = g_off[i] + add;
        g_off[i] = v;
        if (i < n) g_cur[i] = v;
    }
    if (blockIdx.x == 0 && t == 0) g_cur[0] = 0;
}

// ---------------- kernel 5: scatter src ids into dst-CSR order ------------------
__global__ void scatter_kernel(const int* __restrict__ src, const int* __restrict__ dst, int nE) {
    int e = blockIdx.x * blockDim.x + threadIdx.x;
    if (e < nE) {
        int d = dst[e];
        int p = atomicAdd(&g_cur[d], 1);
        g_srcs[p] = src[e];
    }
}

// ---------------- kernel 6: per-node pull attention (one warp per dst node) -----
// K/V gathered as fp16 (8B per lane per edge each), fp32 math + accumulation.
__device__ __forceinline__ float dot4_h(uint2 u, float4 q) {
    float2 a = __half22float2(*reinterpret_cast<__half2*>(&u.x));
    float2 b = __half22float2(*reinterpret_cast<__half2*>(&u.y));
    return a.x * q.x + a.y * q.y + b.x * q.z + b.y * q.w;
}
__device__ __forceinline__ void acc4_h(uint2 u, float s, float4& acc) {
    float2 a = __half22float2(*reinterpret_cast<__half2*>(&u.x));
    float2 b = __half22float2(*reinterpret_cast<__half2*>(&u.y));
    acc.x = fmaf(a.x, s, acc.x);
    acc.y = fmaf(a.y, s, acc.y);
    acc.z = fmaf(b.x, s, acc.z);
    acc.w = fmaf(b.y, s, acc.w);
}

__global__ void __launch_bounds__(256)
consume_kernel(float* __restrict__ out, int nN) {
    int w    = (blockIdx.x * blockDim.x + threadIdx.x) >> 5;
    int lane = threadIdx.x & 31;
    if (w >= nN) return;

    const float4* Q4 = (const float4*)g_Q;
    const uint2*  K2 = (const uint2*)g_Kh;   // 4 halfs per lane
    const uint2*  V2 = (const uint2*)g_Vh;

    int beg = g_off[w];
    int end = g_off[w + 1];

    float4 q   = Q4[(size_t)w * 32 + lane];
    float4 acc = make_float4(0.f, 0.f, 0.f, 0.f);
    float  z   = 0.f;

    int j = beg;
    for (; j + 3 < end; j += 4) {
        int s0 = g_srcs[j];
        int s1 = g_srcs[j + 1];
        int s2 = g_srcs[j + 2];
        int s3 = g_srcs[j + 3];
        uint2 k0 = K2[(size_t)s0 * 32 + lane];
        uint2 k1 = K2[(size_t)s1 * 32 + lane];
        uint2 k2 = K2[(size_t)s2 * 32 + lane];
        uint2 k3 = K2[(size_t)s3 * 32 + lane];
        uint2 v0 = V2[(size_t)s0 * 32 + lane];
        uint2 v1 = V2[(size_t)s1 * 32 + lane];
        uint2 v2 = V2[(size_t)s2 * 32 + lane];
        uint2 v3 = V2[(size_t)s3 * 32 + lane];

        float p0 = dot4_h(k0, q);
        float p1 = dot4_h(k1, q);
        float p2 = dot4_h(k2, q);
        float p3 = dot4_h(k3, q);
        p0 += __shfl_xor_sync(0xffffffffu, p0, 1);
        p0 += __shfl_xor_sync(0xffffffffu, p0, 2);
        p1 += __shfl_xor_sync(0xffffffffu, p1, 1);
        p1 += __shfl_xor_sync(0xffffffffu, p1, 2);
        p2 += __shfl_xor_sync(0xffffffffu, p2, 1);
        p2 += __shfl_xor_sync(0xffffffffu, p2, 2);
        p3 += __shfl_xor_sync(0xffffffffu, p3, 1);
        p3 += __shfl_xor_sync(0xffffffffu, p3, 2);

        float sc0 = __expf(fminf(fmaxf(p0 * 0.25f, -5.f), 5.f));
        float sc1 = __expf(fminf(fmaxf(p1 * 0.25f, -5.f), 5.f));
        float sc2 = __expf(fminf(fmaxf(p2 * 0.25f, -5.f), 5.f));
        float sc3 = __expf(fminf(fmaxf(p3 * 0.25f, -5.f), 5.f));

        acc4_h(v0, sc0, acc);
        acc4_h(v1, sc1, acc);
        acc4_h(v2, sc2, acc);
        acc4_h(v3, sc3, acc);
        z += (sc0 + sc1) + (sc2 + sc3);
    }
    for (; j < end; j++) {
        int s0 = g_srcs[j];
        uint2 k0 = K2[(size_t)s0 * 32 + lane];
        uint2 v0 = V2[(size_t)s0 * 32 + lane];
        float p0 = dot4_h(k0, q);
        p0 += __shfl_xor_sync(0xffffffffu, p0, 1);
        p0 += __shfl_xor_sync(0xffffffffu, p0, 2);
        float sc0 = __expf(fminf(fmaxf(p0 * 0.25f, -5.f), 5.f));
        acc4_h(v0, sc0, acc);
        z += sc0;
    }

    float inv = 1.f / (z + 1e-6f);
    float4 o = make_float4(acc.x * inv, acc.y * inv, acc.z * inv, acc.w * inv);
    *(float4*)(out + (size_t)w * QKV_DIM + lane * 4) = o;
}

// ---------------- launch ---------------------------------------------------------
extern "C" void kernel_launch(void* const* d_in, const int* in_sizes, int n_in,
                              void* d_out, int out_size)
{
    const float* h  = (const float*)d_in[0];
    const float* Wq = (const float*)d_in[1];
    const float* bq = (const float*)d_in[2];
    const float* Wk = (const float*)d_in[3];
    const float* bk = (const float*)d_in[4];
    const float* Wv = (const float*)d_in[5];
    const float* bv = (const float*)d_in[6];
    const int*   src = (const int*)d_in[7];
    const int*   dst = (const int*)d_in[8];

    int nN = in_sizes[0] / IN_DIM;
    int nE = in_sizes[7];
    if (nN > N_NODES_MAX) nN = N_NODES_MAX;
    if (nE > N_EDGES_MAX) nE = N_EDGES_MAX;

    float* out = (float*)d_out;
    int nb = (nN + 1023) / 1024;

    static cudaStream_t s2 = nullptr;
    static cudaEvent_t  evF = nullptr, evJ = nullptr;
    if (!s2) {
        if (cudaStreamCreateWithFlags(&s2, cudaStreamNonBlocking) != cudaSuccess) s2 = nullptr;
        if (s2) {
            if (cudaEventCreateWithFlags(&evF, cudaEventDisableTiming) != cudaSuccess) evF = nullptr;
            if (cudaEventCreateWithFlags(&evJ, cudaEventDisableTiming) != cudaSuccess) evJ = nullptr;
        }
    }
    bool fork = (s2 && evF && evJ);

    dim3 pgrid((nN + 127) / 128, 3);

    if (fork) {
        cudaEventRecord(evF, 0);
        cudaStreamWaitEvent(s2, evF, 0);

        zero_off_kernel<<<(nN + 1 + 255) / 256, 256, 0, s2>>>(nN);
        hist_kernel<<<(nE + 255) / 256, 256, 0, s2>>>(dst, nE);
        block_scan_kernel<<<nb, 1024, 0, s2>>>(nN);
        bsum_scan_kernel<<<1, 32, 0, s2>>>(nb);
        scan_add_kernel<<<nb, 1024, 0, s2>>>(nN);
        scatter_kernel<<<(nE + 255) / 256, 256, 0, s2>>>(src, dst, nE);
        cudaEventRecord(evJ, s2);

        proj_kernel<<<pgrid, 256>>>(h, Wq, bq, Wk, bk, Wv, bv, nN);

        cudaStreamWaitEvent(0, evJ, 0);
    } else {
        zero_off_kernel<<<(nN + 1 + 255) / 256, 256>>>(nN);
        proj_kernel<<<pgrid, 256>>>(h, Wq, bq, Wk, bk, Wv, bv, nN);
        hist_kernel<<<(nE + 255) / 256, 256>>>(dst, nE);
        block_scan_kernel<<<nb, 1024>>>(nN);
        bsum_scan_kernel<<<1, 32>>>(nb);
        scan_add_kernel<<<nb, 1024>>>(nN);
        scatter_kernel<<<(nE + 255) / 256, 256>>>(src, dst, nE);
    }

    int nBlocks = (nN + 7) / 8;
    consume_kernel<<<nBlocks, 256>>>(out, nN);

    (void)n_in; (void)out_size;
}